// round 1
// baseline (speedup 1.0000x reference)
#include <cuda_runtime.h>
#include <math.h>

// ---------------- static scratch (no allocations allowed) ----------------
#define NB 2
#define CQ 64
#define HWA 4096         // 64*64 spatial positions

__device__ float g_fa[NB*CQ*HWA];        // 2 MB
__device__ float g_fb[NB*CQ*HWA];        // 2 MB
__device__ float g_meanA[NB*CQ];
__device__ float g_meanB[NB*CQ];
__device__ float g_fc1[NB*3*128*128];
__device__ float g_fc2[NB*3*64*64];
__device__ float g_warp[NB*3*4096];
__device__ float g_up1[NB*3*128*128];
__device__ float g_c1[NB*3*128*128];
__device__ float g_up2[NB*3*256*256];

// ---------------- 1x1 conv as GEMM: tmp[n,co,p] = sum_ci W[co,ci]*x[n,ci,p] + b[co]
// grid (64 p-tiles, NB), block 256 = (64 p_local) x (4 co-groups of 16)
__global__ void k_gemm1x1(const float* __restrict__ x, const float* __restrict__ W,
                          const float* __restrict__ b, float* __restrict__ out) {
    __shared__ float sW[64][65];  // [co][ci_local]
    int pl  = threadIdx.x & 63;
    int cog = threadIdx.x >> 6;
    int p   = blockIdx.x * 64 + pl;
    int n   = blockIdx.y;
    const float* xn = x + (size_t)n * 256 * HWA;
    float acc[16];
#pragma unroll
    for (int k = 0; k < 16; k++) acc[k] = 0.f;

    for (int ci0 = 0; ci0 < 256; ci0 += 64) {
        __syncthreads();
        for (int i = threadIdx.x; i < 64 * 64; i += 256) {
            int co = i >> 6, cl = i & 63;
            sW[co][cl] = W[co * 256 + ci0 + cl];
        }
        __syncthreads();
#pragma unroll 4
        for (int cl = 0; cl < 64; cl++) {
            float xv = xn[(size_t)(ci0 + cl) * HWA + p];
#pragma unroll
            for (int k = 0; k < 16; k++) acc[k] += sW[cog * 16 + k][cl] * xv;
        }
    }
    float* on = out + (size_t)n * CQ * HWA;
#pragma unroll
    for (int k = 0; k < 16; k++) {
        int co = cog * 16 + k;
        on[(size_t)co * HWA + p] = acc[k] + b[co];
    }
}

// ---------------- instance norm (biased var, eps=1e-5) + leaky relu 0.2, in place.
// one block (256 thr) per plane; 3 passes for numerical safety.
__global__ void k_in_leaky(float* __restrict__ buf, int HW) {
    float* p = buf + (size_t)blockIdx.x * HW;
    int t = threadIdx.x;
    __shared__ float red[256];
    __shared__ float s_mean, s_rstd;

    float s = 0.f;
    for (int i = t; i < HW; i += 256) s += p[i];
    red[t] = s; __syncthreads();
    for (int o = 128; o > 0; o >>= 1) { if (t < o) red[t] += red[t + o]; __syncthreads(); }
    if (t == 0) s_mean = red[0] / (float)HW;
    __syncthreads();
    float mean = s_mean;

    float s2 = 0.f;
    for (int i = t; i < HW; i += 256) { float d = p[i] - mean; s2 += d * d; }
    red[t] = s2; __syncthreads();
    for (int o = 128; o > 0; o >>= 1) { if (t < o) red[t] += red[t + o]; __syncthreads(); }
    if (t == 0) s_rstd = rsqrtf(red[0] / (float)HW + 1e-5f);
    __syncthreads();
    float r = s_rstd;

    for (int i = t; i < HW; i += 256) {
        float v = (p[i] - mean) * r;
        p[i] = v >= 0.f ? v : 0.2f * v;
    }
}

// ---------------- per-(n,c) mean over 4096 (for correlation re-centering)
__global__ void k_rowmean(const float* __restrict__ buf, float* __restrict__ mean) {
    const float* p = buf + (size_t)blockIdx.x * HWA;
    int t = threadIdx.x;
    __shared__ float red[256];
    float s = 0.f;
    for (int i = t; i < HWA; i += 256) s += p[i];
    red[t] = s; __syncthreads();
    for (int o = 128; o > 0; o >>= 1) { if (t < o) red[t] += red[t + o]; __syncthreads(); }
    if (t == 0) mean[blockIdx.x] = red[0] / (float)HWA;
}

// ---------------- center + column L2 normalize, in place.  grid (16, NB), 256 thr
__global__ void k_colnorm(float* __restrict__ buf, const float* __restrict__ mean) {
    int n = blockIdx.y;
    int q = blockIdx.x * 256 + threadIdx.x;
    __shared__ float sm[64];
    if (threadIdx.x < 64) sm[threadIdx.x] = mean[n * 64 + threadIdx.x];
    __syncthreads();
    float* bn = buf + (size_t)n * CQ * HWA;
    float v[64];
    float s = 0.f;
#pragma unroll
    for (int c = 0; c < 64; c++) {
        float t2 = bn[(size_t)c * HWA + q] - sm[c];
        v[c] = t2; s += t2 * t2;
    }
    float inv = 1.f / (sqrtf(s) + 1e-5f);
#pragma unroll
    for (int c = 0; c < 64; c++) bn[(size_t)c * HWA + q] = v[c] * inv;
}

// ---------------- energy GEMM: E[n,p,q] = 100 * sum_c fbN[n,c,p] * faN[n,c,q]
// block tile 128x128, thread tile 8x8, K chunked by 16.  grid (32 q, 32 p, NB), block (16,16)
__global__ void k_energy(const float* __restrict__ fbN, const float* __restrict__ faN,
                         float* __restrict__ E) {
    __shared__ __align__(16) float sA[16][128]; // fa (q dim)
    __shared__ __align__(16) float sB[16][128]; // fb (p dim)
    int n = blockIdx.z;
    const float* A = faN + (size_t)n * CQ * HWA;
    const float* B = fbN + (size_t)n * CQ * HWA;
    float* En = E + (size_t)n * HWA * HWA;
    int q0 = blockIdx.x * 128, p0 = blockIdx.y * 128;
    int tx = threadIdx.x, ty = threadIdx.y;
    int tid = ty * 16 + tx;

    float acc[8][8];
#pragma unroll
    for (int i = 0; i < 8; i++)
#pragma unroll
        for (int j = 0; j < 8; j++) acc[i][j] = 0.f;

    for (int c0 = 0; c0 < 64; c0 += 16) {
        for (int i = tid; i < 16 * 128; i += 256) {
            int r = i >> 7, col = i & 127;
            sA[r][col] = A[(size_t)(c0 + r) * HWA + q0 + col];
            sB[r][col] = B[(size_t)(c0 + r) * HWA + p0 + col];
        }
        __syncthreads();
#pragma unroll
        for (int k = 0; k < 16; k++) {
            float4 a0 = *reinterpret_cast<const float4*>(&sA[k][tx * 8]);
            float4 a1 = *reinterpret_cast<const float4*>(&sA[k][tx * 8 + 4]);
            float4 b0 = *reinterpret_cast<const float4*>(&sB[k][ty * 8]);
            float4 b1 = *reinterpret_cast<const float4*>(&sB[k][ty * 8 + 4]);
            float a[8] = {a0.x, a0.y, a0.z, a0.w, a1.x, a1.y, a1.z, a1.w};
            float bb[8] = {b0.x, b0.y, b0.z, b0.w, b1.x, b1.y, b1.z, b1.w};
#pragma unroll
            for (int i = 0; i < 8; i++)
#pragma unroll
                for (int j = 0; j < 8; j++) acc[i][j] += bb[i] * a[j];
        }
        __syncthreads();
    }
#pragma unroll
    for (int i = 0; i < 8; i++) {
        size_t row = (size_t)(p0 + ty * 8 + i);
        float* Er = En + row * HWA + q0 + tx * 8;
#pragma unroll
        for (int j = 0; j < 8; j++) Er[j] = 100.f * acc[i][j];
    }
}

// ---------------- fused column softmax (over p) + fc_warp einsum.
// block: 256 thr = (32 q_local) x (8 p-groups); grid (128 q-chunks, NB)
__global__ void k_softmax_warp(float* __restrict__ E, const float* __restrict__ fc,
                               float* __restrict__ warp) {
    int ql = threadIdx.x & 31;
    int pg = threadIdx.x >> 5;
    int n = blockIdx.y;
    int q = blockIdx.x * 32 + ql;
    float* En = E + (size_t)n * HWA * HWA;

    // pass 1: online max / sum-exp over this thread's p stripe
    float m = -1e30f, l = 0.f;
    for (int p = pg; p < HWA; p += 8) {
        float e = En[(size_t)p * HWA + q];
        float mn = fmaxf(m, e);
        l = l * __expf(m - mn) + __expf(e - mn);
        m = mn;
    }
    __shared__ float smx[8][32], sl[8][32];
    smx[pg][ql] = m; sl[pg][ql] = l;
    __syncthreads();
    float M = smx[0][ql];
#pragma unroll
    for (int g = 1; g < 8; g++) M = fmaxf(M, smx[g][ql]);
    float L = 0.f;
#pragma unroll
    for (int g = 0; g < 8; g++) L += sl[g][ql] * __expf(smx[g][ql] - M);
    float Li = 1.f / L;

    // pass 2: write corr in place, accumulate fc_warp (3 channels)
    const float* f0 = fc + (size_t)(n * 3 + 0) * HWA;
    const float* f1 = fc + (size_t)(n * 3 + 1) * HWA;
    const float* f2 = fc + (size_t)(n * 3 + 2) * HWA;
    float w0 = 0.f, w1 = 0.f, w2 = 0.f;
    for (int p = pg; p < HWA; p += 8) {
        size_t off = (size_t)p * HWA + q;
        float w = __expf(En[off] - M) * Li;
        En[off] = w;
        w0 += __ldg(f0 + p) * w;
        w1 += __ldg(f1 + p) * w;
        w2 += __ldg(f2 + p) * w;
    }
    __shared__ float sw[3][8][32];
    __syncthreads();
    sw[0][pg][ql] = w0; sw[1][pg][ql] = w1; sw[2][pg][ql] = w2;
    __syncthreads();
    if (pg == 0) {
        float a0 = 0.f, a1 = 0.f, a2 = 0.f;
#pragma unroll
        for (int g = 0; g < 8; g++) { a0 += sw[0][g][ql]; a1 += sw[1][g][ql]; a2 += sw[2][g][ql]; }
        warp[(size_t)(n * 3 + 0) * HWA + q] = a0;
        warp[(size_t)(n * 3 + 1) * HWA + q] = a1;
        warp[(size_t)(n * 3 + 2) * HWA + q] = a2;
    }
}

// ---------------- 3x3 conv, reflect pad 1, stride 2, 3->3 channels
__global__ void k_conv_refl_s2(const float* __restrict__ x, const float* __restrict__ W,
                               const float* __restrict__ b, float* __restrict__ y, int Hin) {
    int Hout = Hin / 2;
    int total = NB * 3 * Hout * Hout;
    int idx = blockIdx.x * 256 + threadIdx.x;
    if (idx >= total) return;
    int ow = idx % Hout; int t = idx / Hout;
    int oh = t % Hout; t /= Hout;
    int co = t % 3; int n = t / 3;
    float s = b[co];
#pragma unroll
    for (int ci = 0; ci < 3; ci++) {
        const float* xp = x + (size_t)((n * 3 + ci) * Hin) * Hin;
#pragma unroll
        for (int kh = 0; kh < 3; kh++) {
            int ih = 2 * oh + kh - 1;
            if (ih < 0) ih = -ih; else if (ih >= Hin) ih = 2 * Hin - 2 - ih;
#pragma unroll
            for (int kw = 0; kw < 3; kw++) {
                int iw = 2 * ow + kw - 1;
                if (iw < 0) iw = -iw; else if (iw >= Hin) iw = 2 * Hin - 2 - iw;
                s += W[((co * 3 + ci) * 3 + kh) * 3 + kw] * __ldg(xp + ih * Hin + iw);
            }
        }
    }
    y[idx] = s;
}

// ---------------- 3x3 conv, zero pad 1, stride 1, 3->3 channels
__global__ void k_conv_zero_s1(const float* __restrict__ x, const float* __restrict__ W,
                               const float* __restrict__ b, float* __restrict__ y, int H) {
    int total = NB * 3 * H * H;
    int idx = blockIdx.x * 256 + threadIdx.x;
    if (idx >= total) return;
    int ow = idx % H; int t = idx / H;
    int oh = t % H; t /= H;
    int co = t % 3; int n = t / 3;
    float s = b[co];
#pragma unroll
    for (int ci = 0; ci < 3; ci++) {
        const float* xp = x + (size_t)((n * 3 + ci) * H) * H;
#pragma unroll
        for (int kh = 0; kh < 3; kh++) {
            int ih = oh + kh - 1;
            if (ih < 0 || ih >= H) continue;
#pragma unroll
            for (int kw = 0; kw < 3; kw++) {
                int iw = ow + kw - 1;
                if (iw < 0 || iw >= H) continue;
                s += W[((co * 3 + ci) * 3 + kh) * 3 + kw] * __ldg(xp + ih * H + iw);
            }
        }
    }
    y[idx] = s;
}

// ---------------- bilinear 2x upsample, align_corners=True
__global__ void k_up2x(const float* __restrict__ x, float* __restrict__ y, int S) {
    int O = 2 * S;
    int total = NB * 3 * O * O;
    int idx = blockIdx.x * 256 + threadIdx.x;
    if (idx >= total) return;
    int ow = idx % O; int t = idx / O;
    int oh = t % O;
    int pl = t / O;  // n*3+c
    float ph = (float)(oh * (S - 1)) / (float)(O - 1);
    float pw = (float)(ow * (S - 1)) / (float)(O - 1);
    int i0 = (int)ph; float fh = ph - (float)i0; int i1 = min(i0 + 1, S - 1);
    int j0 = (int)pw; float fw = pw - (float)j0; int j1 = min(j0 + 1, S - 1);
    const float* xp = x + (size_t)pl * S * S;
    float top = xp[i0 * S + j0] * (1.f - fh) + xp[i1 * S + j0] * fh;
    float bot = xp[i0 * S + j1] * (1.f - fh) + xp[i1 * S + j1] * fh;
    y[idx] = top * (1.f - fw) + bot * fw;
}

// ---------------- host side ----------------
static float* sym(const void* s) {
    void* p = nullptr;
    cudaGetSymbolAddress(&p, s);
    return (float*)p;
}

extern "C" void kernel_launch(void* const* d_in, const int* in_sizes, int n_in,
                              void* d_out, int out_size) {
    const float* fa_raw = (const float*)d_in[0];
    const float* fb_raw = (const float*)d_in[1];
    const float* fc_raw = (const float*)d_in[2];
    const float* Wa  = (const float*)d_in[3];
    const float* ba  = (const float*)d_in[4];
    const float* Wb  = (const float*)d_in[5];
    const float* bb  = (const float*)d_in[6];
    const float* Wc1 = (const float*)d_in[7];
    const float* bc1 = (const float*)d_in[8];
    const float* Wc2 = (const float*)d_in[9];
    const float* bc2 = (const float*)d_in[10];
    const float* Wu1 = (const float*)d_in[11];
    const float* bu1 = (const float*)d_in[12];
    const float* Wu2 = (const float*)d_in[13];
    const float* bu2 = (const float*)d_in[14];

    float* out = (float*)d_out;
    float* fcw  = out;                          // [2,3,256,256]
    float* corr = out + (size_t)NB * 3 * 256 * 256;  // [2,4096,4096]

    float* fa   = sym(g_fa);
    float* fb   = sym(g_fb);
    float* mA   = sym(g_meanA);
    float* mB   = sym(g_meanB);
    float* fc1  = sym(g_fc1);
    float* fc2  = sym(g_fc2);
    float* warp = sym(g_warp);
    float* up1  = sym(g_up1);
    float* c1   = sym(g_c1);
    float* up2  = sym(g_up2);

    // fa / fb feature path
    k_gemm1x1<<<dim3(64, NB), 256>>>(fa_raw, Wa, ba, fa);
    k_gemm1x1<<<dim3(64, NB), 256>>>(fb_raw, Wb, bb, fb);
    k_in_leaky<<<NB * CQ, 256>>>(fa, HWA);
    k_in_leaky<<<NB * CQ, 256>>>(fb, HWA);
    k_rowmean<<<NB * CQ, 256>>>(fa, mA);
    k_rowmean<<<NB * CQ, 256>>>(fb, mB);
    k_colnorm<<<dim3(16, NB), 256>>>(fa, mA);
    k_colnorm<<<dim3(16, NB), 256>>>(fb, mB);

    // fc downsample path
    k_conv_refl_s2<<<(NB * 3 * 128 * 128 + 255) / 256, 256>>>(fc_raw, Wc1, bc1, fc1, 256);
    k_in_leaky<<<NB * 3, 256>>>(fc1, 128 * 128);
    k_conv_refl_s2<<<(NB * 3 * 64 * 64 + 255) / 256, 256>>>(fc1, Wc2, bc2, fc2, 128);
    k_in_leaky<<<NB * 3, 256>>>(fc2, 64 * 64);

    // energy GEMM straight into corr region of d_out
    k_energy<<<dim3(32, 32, NB), dim3(16, 16)>>>(fb, fa, corr);

    // fused column softmax (in place) + fc_warp einsum
    k_softmax_warp<<<dim3(128, NB), 256>>>(corr, fc2, warp);

    // upsample block 1: 64 -> 128
    k_up2x<<<(NB * 3 * 128 * 128 + 255) / 256, 256>>>(warp, up1, 64);
    k_conv_zero_s1<<<(NB * 3 * 128 * 128 + 255) / 256, 256>>>(up1, Wu1, bu1, c1, 128);
    k_in_leaky<<<NB * 3, 256>>>(c1, 128 * 128);

    // upsample block 2: 128 -> 256, final result into d_out fc_warp region
    k_up2x<<<(NB * 3 * 256 * 256 + 255) / 256, 256>>>(c1, up2, 128);
    k_conv_zero_s1<<<(NB * 3 * 256 * 256 + 255) / 256, 256>>>(up2, Wu2, bu2, fcw, 256);
    k_in_leaky<<<NB * 3, 256>>>(fcw, 256 * 256);
}

// round 8
// speedup vs baseline: 1.2949x; 1.2949x over previous
#include <cuda_runtime.h>
#include <cuda_bf16.h>
#include <cstdint>
#include <math.h>

// ---------------- static scratch (no allocations allowed) ----------------
#define NB 2
#define CQ 64
#define HWA 4096         // 64*64 spatial positions

__device__ float g_fa[NB*CQ*HWA];        // fp32 features, pre-norm
__device__ float g_fb[NB*CQ*HWA];
__device__ float g_meanA[NB*CQ];
__device__ float g_meanB[NB*CQ];
__device__ __nv_bfloat16 g_faH[NB*HWA*CQ];  // transposed [q][c] bf16 hi/lo
__device__ __nv_bfloat16 g_faL[NB*HWA*CQ];
__device__ __nv_bfloat16 g_fbH[NB*HWA*CQ];
__device__ __nv_bfloat16 g_fbL[NB*HWA*CQ];
__device__ float g_fc1[NB*3*128*128];
__device__ float g_fc2[NB*3*64*64];
__device__ float g_warp[NB*3*4096];
__device__ float g_up1[NB*3*128*128];
__device__ float g_c1[NB*3*128*128];
__device__ float g_up2[NB*3*256*256];

__device__ __forceinline__ uint32_t smem_u32(const void* p) {
    uint32_t a;
    asm("{ .reg .u64 t; cvta.to.shared.u64 t, %1; cvt.u32.u64 %0, t; }" : "=r"(a) : "l"(p));
    return a;
}

// ---------------- 1x1 conv as GEMM ----------------
__global__ void k_gemm1x1(const float* __restrict__ x, const float* __restrict__ W,
                          const float* __restrict__ b, float* __restrict__ out) {
    __shared__ float sW[64][65];
    int pl  = threadIdx.x & 63;
    int cog = threadIdx.x >> 6;
    int p   = blockIdx.x * 64 + pl;
    int n   = blockIdx.y;
    const float* xn = x + (size_t)n * 256 * HWA;
    float acc[16];
#pragma unroll
    for (int k = 0; k < 16; k++) acc[k] = 0.f;

    for (int ci0 = 0; ci0 < 256; ci0 += 64) {
        __syncthreads();
        for (int i = threadIdx.x; i < 64 * 64; i += 256) {
            int co = i >> 6, cl = i & 63;
            sW[co][cl] = W[co * 256 + ci0 + cl];
        }
        __syncthreads();
#pragma unroll 4
        for (int cl = 0; cl < 64; cl++) {
            float xv = xn[(size_t)(ci0 + cl) * HWA + p];
#pragma unroll
            for (int k = 0; k < 16; k++) acc[k] += sW[cog * 16 + k][cl] * xv;
        }
    }
    float* on = out + (size_t)n * CQ * HWA;
#pragma unroll
    for (int k = 0; k < 16; k++) {
        int co = cog * 16 + k;
        on[(size_t)co * HWA + p] = acc[k] + b[co];
    }
}

// ---------------- instance norm + leaky relu, in place ----------------
__global__ void k_in_leaky(float* __restrict__ buf, int HW) {
    float* p = buf + (size_t)blockIdx.x * HW;
    int t = threadIdx.x;
    __shared__ float red[256];
    __shared__ float s_mean, s_rstd;

    float s = 0.f;
    for (int i = t; i < HW; i += 256) s += p[i];
    red[t] = s; __syncthreads();
    for (int o = 128; o > 0; o >>= 1) { if (t < o) red[t] += red[t + o]; __syncthreads(); }
    if (t == 0) s_mean = red[0] / (float)HW;
    __syncthreads();
    float mean = s_mean;

    float s2 = 0.f;
    for (int i = t; i < HW; i += 256) { float d = p[i] - mean; s2 += d * d; }
    red[t] = s2; __syncthreads();
    for (int o = 128; o > 0; o >>= 1) { if (t < o) red[t] += red[t + o]; __syncthreads(); }
    if (t == 0) s_rstd = rsqrtf(red[0] / (float)HW + 1e-5f);
    __syncthreads();
    float r = s_rstd;

    for (int i = t; i < HW; i += 256) {
        float v = (p[i] - mean) * r;
        p[i] = v >= 0.f ? v : 0.2f * v;
    }
}

// ---------------- per-(n,c) spatial mean ----------------
__global__ void k_rowmean(const float* __restrict__ buf, float* __restrict__ mean) {
    const float* p = buf + (size_t)blockIdx.x * HWA;
    int t = threadIdx.x;
    __shared__ float red[256];
    float s = 0.f;
    for (int i = t; i < HWA; i += 256) s += p[i];
    red[t] = s; __syncthreads();
    for (int o = 128; o > 0; o >>= 1) { if (t < o) red[t] += red[t + o]; __syncthreads(); }
    if (t == 0) mean[blockIdx.x] = red[0] / (float)HWA;
}

// ---------------- center + column L2 normalize, emit transposed bf16 hi/lo ----------------
__global__ void k_colnorm_bf16(const float* __restrict__ buf, const float* __restrict__ mean,
                               __nv_bfloat16* __restrict__ oH, __nv_bfloat16* __restrict__ oL) {
    int n = blockIdx.y;
    int q = blockIdx.x * 256 + threadIdx.x;
    __shared__ float sm[64];
    if (threadIdx.x < 64) sm[threadIdx.x] = mean[n * 64 + threadIdx.x];
    __syncthreads();
    const float* bn = buf + (size_t)n * CQ * HWA;
    float v[64];
    float s = 0.f;
#pragma unroll
    for (int c = 0; c < 64; c++) {
        float t2 = bn[(size_t)c * HWA + q] - sm[c];
        v[c] = t2; s += t2 * t2;
    }
    float inv = 1.f / (sqrtf(s) + 1e-5f);
    __align__(16) __nv_bfloat16 hb[64];
    __align__(16) __nv_bfloat16 lb[64];
#pragma unroll
    for (int c = 0; c < 64; c++) {
        float f = v[c] * inv;
        __nv_bfloat16 h = __float2bfloat16(f);
        hb[c] = h;
        lb[c] = __float2bfloat16(f - __bfloat162float(h));
    }
    uint4* dH = (uint4*)(oH + ((size_t)n * HWA + q) * 64);
    uint4* dL = (uint4*)(oL + ((size_t)n * HWA + q) * 64);
#pragma unroll
    for (int i = 0; i < 8; i++) {
        dH[i] = ((const uint4*)hb)[i];
        dL[i] = ((const uint4*)lb)[i];
    }
}

// ---------------- energy GEMM via mma.sync bf16 hi/lo split (3 passes) ----------------
// E[n,p,q] = 100 * sum_c fb_t[p][c] * fa_t[q][c]
// CTA tile 128(p) x 128(q), K=64.  8 warps: warp = 64(m) x 32(n).
// smem: 4 tiles of [128 rows][64 bf16 = 128B], XOR-swizzled in 16B chunks.
#define EGY_DSMEM (4 * 16384)

__device__ __forceinline__ void ldsm_x4(uint32_t& r0, uint32_t& r1, uint32_t& r2, uint32_t& r3,
                                        uint32_t addr) {
    asm volatile("ldmatrix.sync.aligned.m8n8.x4.shared.b16 {%0,%1,%2,%3}, [%4];"
                 : "=r"(r0), "=r"(r1), "=r"(r2), "=r"(r3) : "r"(addr));
}
__device__ __forceinline__ void mma16816(float& d0, float& d1, float& d2, float& d3,
                                         uint32_t a0, uint32_t a1, uint32_t a2, uint32_t a3,
                                         uint32_t b0, uint32_t b1) {
    asm volatile(
        "mma.sync.aligned.m16n8k16.row.col.f32.bf16.bf16.f32 "
        "{%0,%1,%2,%3}, {%4,%5,%6,%7}, {%8,%9}, {%0,%1,%2,%3};"
        : "+f"(d0), "+f"(d1), "+f"(d2), "+f"(d3)
        : "r"(a0), "r"(a1), "r"(a2), "r"(a3), "r"(b0), "r"(b1));
}

__global__ void __launch_bounds__(256, 2)
k_energy_mma(const __nv_bfloat16* __restrict__ AH, const __nv_bfloat16* __restrict__ AL,
             const __nv_bfloat16* __restrict__ BH, const __nv_bfloat16* __restrict__ BL,
             float* __restrict__ E) {
    extern __shared__ __align__(16) char smem[];
    const int tid = threadIdx.x;
    const int wid = tid >> 5, lane = tid & 31;
    const int wm = wid & 1, wn = wid >> 1;        // warp tile: rows wm*64, cols wn*32
    const int n = blockIdx.z;
    const int q0 = blockIdx.x * 128, p0 = blockIdx.y * 128;

    const int T_AH = 0, T_AL = 16384, T_BH = 32768, T_BL = 49152;

    // gmem -> smem with 16B-chunk XOR swizzle (chunk' = chunk ^ (row & 7))
    {
        const uint4* src[4] = {
            (const uint4*)(AH + ((size_t)n * HWA + p0) * 64),
            (const uint4*)(AL + ((size_t)n * HWA + p0) * 64),
            (const uint4*)(BH + ((size_t)n * HWA + q0) * 64),
            (const uint4*)(BL + ((size_t)n * HWA + q0) * 64)};
        uint4* dst[4] = {(uint4*)(smem + T_AH), (uint4*)(smem + T_AL),
                         (uint4*)(smem + T_BH), (uint4*)(smem + T_BL)};
#pragma unroll
        for (int t4 = 0; t4 < 4; t4++) {
#pragma unroll
            for (int i = 0; i < 4; i++) {
                int g = tid + i * 256;            // 1024 uint4 per tile
                int row = g >> 3, ch = g & 7;
                dst[t4][row * 8 + (ch ^ (row & 7))] = src[t4][g];
            }
        }
    }
    __syncthreads();

    const uint32_t sbase = smem_u32(smem);
    float acc[4][4][4];                            // [mi][ni][reg]
#pragma unroll
    for (int a = 0; a < 4; a++)
#pragma unroll
        for (int b = 0; b < 4; b++)
#pragma unroll
            for (int r = 0; r < 4; r++) acc[a][b][r] = 0.f;

    const int aoff[3] = {T_AH, T_AH, T_AL};
    const int boff[3] = {T_BH, T_BL, T_BH};

#pragma unroll
    for (int pass = 0; pass < 3; pass++) {
        uint32_t abase = sbase + aoff[pass];
        uint32_t bbase = sbase + boff[pass];
#pragma unroll
        for (int k0 = 0; k0 < 64; k0 += 16) {
            int cbase = k0 >> 3;                   // 16B chunk index of k0
            // A frags: 4 m16 tiles
            uint32_t a[4][4];
#pragma unroll
            for (int mi = 0; mi < 4; mi++) {
                int row = wm * 64 + mi * 16 + (lane & 15);
                int ch = cbase + (lane >> 4);
                uint32_t addr = abase + row * 128 + ((ch ^ (row & 7)) << 4);
                ldsm_x4(a[mi][0], a[mi][1], a[mi][2], a[mi][3], addr);
            }
            // B frags: 2 x4 loads cover 4 n8 tiles
            uint32_t b[4][2];
#pragma unroll
            for (int np = 0; np < 2; np++) {
                int row = wn * 32 + np * 16 + (lane & 7) + ((lane >> 4) << 3);
                int ch = cbase + ((lane >> 3) & 1);
                uint32_t addr = bbase + row * 128 + ((ch ^ (row & 7)) << 4);
                uint32_t r0, r1, r2, r3;
                ldsm_x4(r0, r1, r2, r3, addr);
                b[np * 2 + 0][0] = r0; b[np * 2 + 0][1] = r1;
                b[np * 2 + 1][0] = r2; b[np * 2 + 1][1] = r3;
            }
#pragma unroll
            for (int mi = 0; mi < 4; mi++)
#pragma unroll
                for (int ni = 0; ni < 4; ni++)
                    mma16816(acc[mi][ni][0], acc[mi][ni][1], acc[mi][ni][2], acc[mi][ni][3],
                             a[mi][0], a[mi][1], a[mi][2], a[mi][3],
                             b[ni][0], b[ni][1]);
        }
    }

    // epilogue: scale by 100, write to E
    float* En = E + (size_t)n * HWA * HWA;
    int rbase = p0 + wm * 64 + (lane >> 2);
    int cbase2 = q0 + wn * 32 + (lane & 3) * 2;
#pragma unroll
    for (int mi = 0; mi < 4; mi++) {
#pragma unroll
        for (int ni = 0; ni < 4; ni++) {
            float2 v0 = make_float2(100.f * acc[mi][ni][0], 100.f * acc[mi][ni][1]);
            float2 v1 = make_float2(100.f * acc[mi][ni][2], 100.f * acc[mi][ni][3]);
            size_t r0 = (size_t)(rbase + mi * 16) * HWA + cbase2 + ni * 8;
            size_t r1 = r0 + 8 * HWA;
            *(float2*)(En + r0) = v0;
            *(float2*)(En + r1) = v1;
        }
    }
}

// ---------------- fused column softmax + fc_warp einsum ----------------
__global__ void k_softmax_warp(float* __restrict__ E, const float* __restrict__ fc,
                               float* __restrict__ warp) {
    int ql = threadIdx.x & 31;
    int pg = threadIdx.x >> 5;
    int n = blockIdx.y;
    int q = blockIdx.x * 32 + ql;
    float* En = E + (size_t)n * HWA * HWA;

    float m = -1e30f, l = 0.f;
#pragma unroll 4
    for (int p = pg; p < HWA; p += 8) {
        float e = En[(size_t)p * HWA + q];
        float mn = fmaxf(m, e);
        l = l * __expf(m - mn) + __expf(e - mn);
        m = mn;
    }
    __shared__ float smx[8][32], sl[8][32];
    smx[pg][ql] = m; sl[pg][ql] = l;
    __syncthreads();
    float M = smx[0][ql];
#pragma unroll
    for (int g = 1; g < 8; g++) M = fmaxf(M, smx[g][ql]);
    float L = 0.f;
#pragma unroll
    for (int g = 0; g < 8; g++) L += sl[g][ql] * __expf(smx[g][ql] - M);
    float Li = 1.f / L;

    const float* f0 = fc + (size_t)(n * 3 + 0) * HWA;
    const float* f1 = fc + (size_t)(n * 3 + 1) * HWA;
    const float* f2 = fc + (size_t)(n * 3 + 2) * HWA;
    float w0 = 0.f, w1 = 0.f, w2 = 0.f;
#pragma unroll 4
    for (int p = pg; p < HWA; p += 8) {
        size_t off = (size_t)p * HWA + q;
        float w = __expf(En[off] - M) * Li;
        En[off] = w;
        w0 += __ldg(f0 + p) * w;
        w1 += __ldg(f1 + p) * w;
        w2 += __ldg(f2 + p) * w;
    }
    __shared__ float sw[3][8][32];
    __syncthreads();
    sw[0][pg][ql] = w0; sw[1][pg][ql] = w1; sw[2][pg][ql] = w2;
    __syncthreads();
    if (pg == 0) {
        float a0 = 0.f, a1 = 0.f, a2 = 0.f;
#pragma unroll
        for (int g = 0; g < 8; g++) { a0 += sw[0][g][ql]; a1 += sw[1][g][ql]; a2 += sw[2][g][ql]; }
        warp[(size_t)(n * 3 + 0) * HWA + q] = a0;
        warp[(size_t)(n * 3 + 1) * HWA + q] = a1;
        warp[(size_t)(n * 3 + 2) * HWA + q] = a2;
    }
}

// ---------------- 3x3 conv, reflect pad 1, stride 2, 3->3 channels ----------------
__global__ void k_conv_refl_s2(const float* __restrict__ x, const float* __restrict__ W,
                               const float* __restrict__ b, float* __restrict__ y, int Hin) {
    int Hout = Hin / 2;
    int total = NB * 3 * Hout * Hout;
    int idx = blockIdx.x * 256 + threadIdx.x;
    if (idx >= total) return;
    int ow = idx % Hout; int t = idx / Hout;
    int oh = t % Hout; t /= Hout;
    int co = t % 3; int n = t / 3;
    float s = b[co];
#pragma unroll
    for (int ci = 0; ci < 3; ci++) {
        const float* xp = x + (size_t)((n * 3 + ci) * Hin) * Hin;
#pragma unroll
        for (int kh = 0; kh < 3; kh++) {
            int ih = 2 * oh + kh - 1;
            if (ih < 0) ih = -ih; else if (ih >= Hin) ih = 2 * Hin - 2 - ih;
#pragma unroll
            for (int kw = 0; kw < 3; kw++) {
                int iw = 2 * ow + kw - 1;
                if (iw < 0) iw = -iw; else if (iw >= Hin) iw = 2 * Hin - 2 - iw;
                s += W[((co * 3 + ci) * 3 + kh) * 3 + kw] * __ldg(xp + ih * Hin + iw);
            }
        }
    }
    y[idx] = s;
}

// ---------------- 3x3 conv, zero pad 1, stride 1, 3->3 channels ----------------
__global__ void k_conv_zero_s1(const float* __restrict__ x, const float* __restrict__ W,
                               const float* __restrict__ b, float* __restrict__ y, int H) {
    int total = NB * 3 * H * H;
    int idx = blockIdx.x * 256 + threadIdx.x;
    if (idx >= total) return;
    int ow = idx % H; int t = idx / H;
    int oh = t % H; t /= H;
    int co = t % 3; int n = t / 3;
    float s = b[co];
#pragma unroll
    for (int ci = 0; ci < 3; ci++) {
        const float* xp = x + (size_t)((n * 3 + ci) * H) * H;
#pragma unroll
        for (int kh = 0; kh < 3; kh++) {
            int ih = oh + kh - 1;
            if (ih < 0 || ih >= H) continue;
#pragma unroll
            for (int kw = 0; kw < 3; kw++) {
                int iw = ow + kw - 1;
                if (iw < 0 || iw >= H) continue;
                s += W[((co * 3 + ci) * 3 + kh) * 3 + kw] * __ldg(xp + ih * H + iw);
            }
        }
    }
    y[idx] = s;
}

// ---------------- bilinear 2x upsample, align_corners=True ----------------
__global__ void k_up2x(const float* __restrict__ x, float* __restrict__ y, int S) {
    int O = 2 * S;
    int total = NB * 3 * O * O;
    int idx = blockIdx.x * 256 + threadIdx.x;
    if (idx >= total) return;
    int ow = idx % O; int t = idx / O;
    int oh = t % O;
    int pl = t / O;  // n*3+c
    float ph = (float)(oh * (S - 1)) / (float)(O - 1);
    float pw = (float)(ow * (S - 1)) / (float)(O - 1);
    int i0 = (int)ph; float fh = ph - (float)i0; int i1 = min(i0 + 1, S - 1);
    int j0 = (int)pw; float fw = pw - (float)j0; int j1 = min(j0 + 1, S - 1);
    const float* xp = x + (size_t)pl * S * S;
    float top = xp[i0 * S + j0] * (1.f - fh) + xp[i1 * S + j0] * fh;
    float bot = xp[i0 * S + j1] * (1.f - fh) + xp[i1 * S + j1] * fh;
    y[idx] = top * (1.f - fw) + bot * fw;
}

// ---------------- host side ----------------
static float* symf(const void* s) {
    void* p = nullptr;
    cudaGetSymbolAddress(&p, s);
    return (float*)p;
}
static __nv_bfloat16* symb(const void* s) {
    void* p = nullptr;
    cudaGetSymbolAddress(&p, s);
    return (__nv_bfloat16*)p;
}

extern "C" void kernel_launch(void* const* d_in, const int* in_sizes, int n_in,
                              void* d_out, int out_size) {
    const float* fa_raw = (const float*)d_in[0];
    const float* fb_raw = (const float*)d_in[1];
    const float* fc_raw = (const float*)d_in[2];
    const float* Wa  = (const float*)d_in[3];
    const float* ba  = (const float*)d_in[4];
    const float* Wb  = (const float*)d_in[5];
    const float* bb  = (const float*)d_in[6];
    const float* Wc1 = (const float*)d_in[7];
    const float* bc1 = (const float*)d_in[8];
    const float* Wc2 = (const float*)d_in[9];
    const float* bc2 = (const float*)d_in[10];
    const float* Wu1 = (const float*)d_in[11];
    const float* bu1 = (const float*)d_in[12];
    const float* Wu2 = (const float*)d_in[13];
    const float* bu2 = (const float*)d_in[14];

    float* out = (float*)d_out;
    float* fcw  = out;                               // [2,3,256,256]
    float* corr = out + (size_t)NB * 3 * 256 * 256;  // [2,4096,4096]

    float* fa   = symf(g_fa);
    float* fb   = symf(g_fb);
    float* mA   = symf(g_meanA);
    float* mB   = symf(g_meanB);
    __nv_bfloat16* faH = symb(g_faH);
    __nv_bfloat16* faL = symb(g_faL);
    __nv_bfloat16* fbH = symb(g_fbH);
    __nv_bfloat16* fbL = symb(g_fbL);
    float* fc1  = symf(g_fc1);
    float* fc2  = symf(g_fc2);
    float* warp = symf(g_warp);
    float* up1  = symf(g_up1);
    float* c1   = symf(g_c1);
    float* up2  = symf(g_up2);

    // idempotent, deterministic, not a stream op — safe under graph capture
    cudaFuncSetAttribute(k_energy_mma, cudaFuncAttributeMaxDynamicSharedMemorySize, EGY_DSMEM);

    // fa / fb feature path
    k_gemm1x1<<<dim3(64, NB), 256>>>(fa_raw, Wa, ba, fa);
    k_gemm1x1<<<dim3(64, NB), 256>>>(fb_raw, Wb, bb, fb);
    k_in_leaky<<<NB * CQ, 256>>>(fa, HWA);
    k_in_leaky<<<NB * CQ, 256>>>(fb, HWA);
    k_rowmean<<<NB * CQ, 256>>>(fa, mA);
    k_rowmean<<<NB * CQ, 256>>>(fb, mB);
    k_colnorm_bf16<<<dim3(16, NB), 256>>>(fa, mA, faH, faL);
    k_colnorm_bf16<<<dim3(16, NB), 256>>>(fb, mB, fbH, fbL);

    // fc downsample path
    k_conv_refl_s2<<<(NB * 3 * 128 * 128 + 255) / 256, 256>>>(fc_raw, Wc1, bc1, fc1, 256);
    k_in_leaky<<<NB * 3, 256>>>(fc1, 128 * 128);
    k_conv_refl_s2<<<(NB * 3 * 64 * 64 + 255) / 256, 256>>>(fc1, Wc2, bc2, fc2, 128);
    k_in_leaky<<<NB * 3, 256>>>(fc2, 64 * 64);

    // energy GEMM (mma.sync bf16-split) straight into corr region of d_out
    k_energy_mma<<<dim3(32, 32, NB), 256, EGY_DSMEM>>>(fbH, fbL, faH, faL, corr);

    // fused column softmax (in place) + fc_warp einsum
    k_softmax_warp<<<dim3(128, NB), 256>>>(corr, fc2, warp);

    // upsample block 1: 64 -> 128
    k_up2x<<<(NB * 3 * 128 * 128 + 255) / 256, 256>>>(warp, up1, 64);
    k_conv_zero_s1<<<(NB * 3 * 128 * 128 + 255) / 256, 256>>>(up1, Wu1, bu1, c1, 128);
    k_in_leaky<<<NB * 3, 256>>>(c1, 128 * 128);

    // upsample block 2: 128 -> 256, final result into d_out fc_warp region
    k_up2x<<<(NB * 3 * 256 * 256 + 255) / 256, 256>>>(c1, up2, 128);
    k_conv_zero_s1<<<(NB * 3 * 256 * 256 + 255) / 256, 256>>>(up2, Wu2, bu2, fcw, 256);
    k_in_leaky<<<NB * 3, 256>>>(fcw, 256 * 256);
}